// round 3
// baseline (speedup 1.0000x reference)
#include <cuda_runtime.h>

#define N_NODES 50000
#define N_EDGES 400000
#define DIM     128
#define WSTRIDE 132            // padded smem stride (floats): conflict-free LDS.128
#define ROWS_PER_BLOCK 128
#define GTHREADS 256

// scratch (no allocations allowed)
__device__ float g_h  [(size_t)N_NODES * DIM];
__device__ float g_agg[(size_t)N_NODES * DIM];
__device__ float g_deg[N_NODES];
__device__ int   g_is64;

// ---------------------------------------------------------------------------
// Edge-index dtype detection: reference declares int64, but JAX default
// config downcasts to int32. Interpreting int32 data as int64 yields values
// with a random nonzero high word -> out of range. Deterministic.
// ---------------------------------------------------------------------------
__global__ void detect_kernel(const void* eiv)
{
    const long long* p = (const long long*)eiv;
    int ok64 = 1;
    for (int i = 0; i < 64; ++i) {
        long long v = p[i];
        if (v < 0 || v >= N_NODES) { ok64 = 0; break; }
    }
    g_is64 = ok64;
}

// ---------------------------------------------------------------------------
// GEMM: Y[r][c] = act( sum_k Z[r][k] * W[c][k] + bias[c] )
// FIRST:  Z = x,             Y = g_h (relu), also zeroes g_agg / g_deg rows
// !FIRST: Z = g_agg/deg+g_h, Y = out (no relu)
// Per-warp: 4 rows x 128 cols; per-lane 4x4 register tile (cols c0..c0+3).
// ---------------------------------------------------------------------------
template<bool FIRST>
__global__ void __launch_bounds__(GTHREADS, 2)
gemm128_kernel(const float* __restrict__ Zext,
               const float* __restrict__ W,
               const float* __restrict__ bias,
               float* __restrict__ Yext)
{
    extern __shared__ float Wsm[];          // WSTRIDE*DIM floats (~66KB)
    __shared__ float zr[32][DIM];           // 32-row input tile (16KB)

    const float* Z = FIRST ? Zext : g_h;
    float*       Y = FIRST ? g_h  : Yext;

    const int tid = threadIdx.x;

    // Transposed W load: Wsm[k*WSTRIDE + c] = W[c*DIM + k]
    for (int i = tid; i < DIM * DIM; i += GTHREADS) {
        int c = i >> 7, k = i & 127;
        Wsm[k * WSTRIDE + c] = W[i];
    }

    const int lane = tid & 31, warp = tid >> 5;
    const int c0 = lane * 4;
    const float4 b4 = *(const float4*)(bias + c0);
    const int row_base = blockIdx.x * ROWS_PER_BLOCK;

    for (int it = 0; it < ROWS_PER_BLOCK / 32; ++it) {
        const int r0 = row_base + it * 32;

        __syncthreads();   // zr reuse fence (also covers W fill on iter 0)

        // ---- fill zr[32][128] cooperatively (float4 per thread x4) ----
        #pragma unroll
        for (int j = 0; j < 4; ++j) {
            int idx = tid + j * GTHREADS;       // 0..1023
            int rr  = idx >> 5;                 // 0..31
            int kk  = (idx & 31) * 4;           // 0..124
            int gr  = r0 + rr;
            float4 v = make_float4(0.f, 0.f, 0.f, 0.f);
            if (gr < N_NODES) {
                v = *(const float4*)(Z + (size_t)gr * DIM + kk);
                if (!FIRST) {
                    float4 a = *(const float4*)(g_agg + (size_t)gr * DIM + kk);
                    float inv = 1.0f / fmaxf(g_deg[gr], 1.0f);
                    v.x += a.x * inv; v.y += a.y * inv;
                    v.z += a.z * inv; v.w += a.w * inv;
                }
            }
            *(float4*)(&zr[rr][kk]) = v;
        }
        __syncthreads();

        // ---- compute 4 rows per warp, 4 cols per lane ----
        const int rr0 = warp * 4;
        float4 acc[4];
        #pragma unroll
        for (int r = 0; r < 4; ++r) acc[r] = b4;

        #pragma unroll
        for (int k = 0; k < DIM; k += 4) {
            float4 z0 = *(const float4*)(&zr[rr0 + 0][k]);
            float4 z1 = *(const float4*)(&zr[rr0 + 1][k]);
            float4 z2 = *(const float4*)(&zr[rr0 + 2][k]);
            float4 z3 = *(const float4*)(&zr[rr0 + 3][k]);
            #pragma unroll
            for (int kk = 0; kk < 4; ++kk) {
                float4 w = *(const float4*)(&Wsm[(k + kk) * WSTRIDE + c0]);
                float s0 = (&z0.x)[kk];
                float s1 = (&z1.x)[kk];
                float s2 = (&z2.x)[kk];
                float s3 = (&z3.x)[kk];
                acc[0].x += s0 * w.x; acc[0].y += s0 * w.y; acc[0].z += s0 * w.z; acc[0].w += s0 * w.w;
                acc[1].x += s1 * w.x; acc[1].y += s1 * w.y; acc[1].z += s1 * w.z; acc[1].w += s1 * w.w;
                acc[2].x += s2 * w.x; acc[2].y += s2 * w.y; acc[2].z += s2 * w.z; acc[2].w += s2 * w.w;
                acc[3].x += s3 * w.x; acc[3].y += s3 * w.y; acc[3].z += s3 * w.z; acc[3].w += s3 * w.w;
            }
        }

        // ---- store ----
        #pragma unroll
        for (int r = 0; r < 4; ++r) {
            int gr = r0 + rr0 + r;
            if (gr < N_NODES) {
                float4 o = acc[r];
                if (FIRST) {
                    o.x = fmaxf(o.x, 0.f); o.y = fmaxf(o.y, 0.f);
                    o.z = fmaxf(o.z, 0.f); o.w = fmaxf(o.w, 0.f);
                }
                *(float4*)(Y + (size_t)gr * DIM + c0) = o;
                if (FIRST) {
                    *(float4*)(g_agg + (size_t)gr * DIM + c0) =
                        make_float4(0.f, 0.f, 0.f, 0.f);
                    if (lane == 0) g_deg[gr] = 0.f;
                }
            }
        }
    }
}

// ---------------------------------------------------------------------------
// Scatter: one warp per edge. Lane l moves float4 at col 4l.
// Vectorized no-return reduction red.global.add.v4.f32 (sm_90+).
// Handles int32 or int64 edge_index via g_is64 flag; bounds-guarded.
// ---------------------------------------------------------------------------
__global__ void __launch_bounds__(256)
scatter_kernel(const void* __restrict__ eiv)
{
    int e    = (blockIdx.x * blockDim.x + threadIdx.x) >> 5;
    int lane = threadIdx.x & 31;
    if (e >= N_EDGES) return;

    long long s, d;
    if (g_is64) {
        const long long* ei = (const long long*)eiv;
        s = __ldg(ei + e);
        d = __ldg(ei + N_EDGES + e);
    } else {
        const int* ei = (const int*)eiv;
        s = __ldg(ei + e);
        d = __ldg(ei + N_EDGES + e);
    }
    if ((unsigned long long)s >= N_NODES || (unsigned long long)d >= N_NODES)
        return;

    float4 v = *(const float4*)(g_h + (size_t)s * DIM + lane * 4);
    float* dst = g_agg + (size_t)d * DIM + lane * 4;
    asm volatile("red.global.add.v4.f32 [%0], {%1,%2,%3,%4};"
                 :: "l"(dst), "f"(v.x), "f"(v.y), "f"(v.z), "f"(v.w)
                 : "memory");
    if (lane == 0) atomicAdd(g_deg + d, 1.0f);
}

// ---------------------------------------------------------------------------
extern "C" void kernel_launch(void* const* d_in, const int* in_sizes, int n_in,
                              void* d_out, int out_size)
{
    const float* x  = (const float*)d_in[0];
    const void*  ei = d_in[1];
    const float* W1 = (const float*)d_in[2];
    const float* b1 = (const float*)d_in[3];
    const float* W2 = (const float*)d_in[4];
    const float* b2 = (const float*)d_in[5];
    float*       out = (float*)d_out;

    const int smem = WSTRIDE * DIM * (int)sizeof(float);   // 67584 B
    cudaFuncSetAttribute(gemm128_kernel<true>,
                         cudaFuncAttributeMaxDynamicSharedMemorySize, smem);
    cudaFuncSetAttribute(gemm128_kernel<false>,
                         cudaFuncAttributeMaxDynamicSharedMemorySize, smem);

    const int gblocks = (N_NODES + ROWS_PER_BLOCK - 1) / ROWS_PER_BLOCK;  // 391

    // 0) detect edge_index dtype (int32 vs int64)
    detect_kernel<<<1, 1>>>(ei);
    // 1) h = relu(x W1^T + b1); zero agg/deg
    gemm128_kernel<true><<<gblocks, GTHREADS, smem>>>(x, W1, b1, nullptr);
    // 2) agg[dst] += h[src]; deg[dst] += 1
    scatter_kernel<<<(N_EDGES * 32 + 255) / 256, 256>>>(ei);
    // 3) out = (agg/deg + h) W2^T + b2
    gemm128_kernel<false><<<gblocks, GTHREADS, smem>>>(nullptr, W2, b2, out);
}